// round 2
// baseline (speedup 1.0000x reference)
#include <cuda_runtime.h>
#include <math.h>

#define L 2048
#define Bb 2
#define Dd 1024
#define Hh 16
#define DK 64
#define DV 64
#define SPAN 128
#define LN_EPS 1e-5f

#define MROWS (L * Bb)          // 4096
#define LBD ((size_t)L * Bb * Dd)               // 4,194,304
#define ATTN_ELEMS ((size_t)Hh * Bb * L * L)    // 134,217,728

// ---------------- scratch (device globals; no allocation) ----------------
__device__ float g_q[Hh * Bb * L * DK];
__device__ float g_k[Hh * Bb * L * DK];
__device__ float g_v[Hh * Bb * L * DV];
__device__ float g_ctx[MROWS * Dd];
__device__ float g_yp[MROWS * Dd];

// ---------------- 128x128x8 SGEMM, 8x8 register tile ----------------
// MODE 0: out[(h*B+b)*L + l][k] permuted QKV write (row m = l*B+b, col n = h*64+k)
// MODE 1: out[m*N+n] = acc + bias[n] + resid[m*N+n]
template <int MODE>
__global__ __launch_bounds__(256) void sgemm128(
    const float* __restrict__ A, const float* __restrict__ B,
    const float* __restrict__ bias, const float* __restrict__ resid,
    float* __restrict__ out, int M, int N, int K)
{
    __shared__ float As[8][128];
    __shared__ float Bs[8][128];

    const int tid = threadIdx.x;
    const int tx = tid & 15;        // 0..15 -> col group
    const int ty = tid >> 4;        // 0..15 -> row group
    const int bm = blockIdx.y * 128;
    const int bn = blockIdx.x * 128;

    const int arow = tid >> 1;          // 0..127
    const int ac4  = (tid & 1) * 4;     // 0 or 4
    const int brow = tid >> 5;          // 0..7
    const int bc4  = (tid & 31) * 4;    // 0..124

    const float* Aptr = A + (size_t)(bm + arow) * K + ac4;
    const float* Bptr = B + (size_t)brow * N + bn + bc4;

    float acc[8][8];
#pragma unroll
    for (int i = 0; i < 8; i++)
#pragma unroll
        for (int j = 0; j < 8; j++) acc[i][j] = 0.f;

    for (int kt = 0; kt < K; kt += 8) {
        float4 av = *(const float4*)(Aptr + kt);
        float4 bv = *(const float4*)(Bptr + (size_t)kt * N);
        __syncthreads();
        As[ac4 + 0][arow] = av.x;
        As[ac4 + 1][arow] = av.y;
        As[ac4 + 2][arow] = av.z;
        As[ac4 + 3][arow] = av.w;
        *(float4*)&Bs[brow][bc4] = bv;
        __syncthreads();

#pragma unroll
        for (int kk = 0; kk < 8; kk++) {
            float4 a0 = *(float4*)&As[kk][ty * 8];
            float4 a1 = *(float4*)&As[kk][ty * 8 + 4];
            float4 b0 = *(float4*)&Bs[kk][tx * 8];
            float4 b1 = *(float4*)&Bs[kk][tx * 8 + 4];
            float a[8] = {a0.x, a0.y, a0.z, a0.w, a1.x, a1.y, a1.z, a1.w};
            float b[8] = {b0.x, b0.y, b0.z, b0.w, b1.x, b1.y, b1.z, b1.w};
#pragma unroll
            for (int i = 0; i < 8; i++)
#pragma unroll
                for (int j = 0; j < 8; j++) acc[i][j] += a[i] * b[j];
        }
    }

#pragma unroll
    for (int i = 0; i < 8; i++) {
        const int m = bm + ty * 8 + i;
#pragma unroll
        for (int j = 0; j < 8; j++) {
            const int n = bn + tx * 8 + j;
            float val = acc[i][j] + bias[n];
            if (MODE == 0) {
                const int l = m >> 1;       // B = 2
                const int b = m & 1;
                const int h = n >> 6;       // DK = 64
                const int k = n & 63;
                out[((size_t)(h * Bb + b) * L + l) * 64 + k] = val;
            } else {
                val += resid[(size_t)m * N + n];
                out[(size_t)m * N + n] = val;
            }
        }
    }
}

// ---------------- banded attention: 64 query rows per CTA ----------------
// smem: Qs[64][65] | KVs[320][65] | Ss[64][321]
#define SMEM_ATTN_FLOATS (64 * 65 + 320 * 65 + 64 * 321)
#define SMEM_ATTN_BYTES (SMEM_ATTN_FLOATS * 4)

__global__ __launch_bounds__(256) void attn_kernel(float* __restrict__ attn_out,
                                                   int write_attn)
{
    extern __shared__ float sm[];
    float* Qs  = sm;                 // 64*65
    float* KVs = sm + 64 * 65;       // 320*65
    float* Ss  = KVs + 320 * 65;     // 64*321

    const int tid = threadIdx.x;
    const int h = blockIdx.z;
    const int b = blockIdx.y;
    const int i0 = blockIdx.x * 64;

    const int jlo = max(0, i0 - SPAN);
    const int jhi = min(L - 1, i0 + 63 + SPAN);
    const int nW = jhi - jlo + 1;    // <= 320

    const float* qbase = g_q + (size_t)(h * Bb + b) * L * 64;
    const float* kbase = g_k + (size_t)(h * Bb + b) * L * 64;
    const float* vbase = g_v + (size_t)(h * Bb + b) * L * 64;

    // load Q tile
    for (int idx = tid; idx < 64 * 64; idx += 256)
        Qs[(idx >> 6) * 65 + (idx & 63)] = qbase[(size_t)i0 * 64 + idx];
    // load K window
    for (int idx = tid; idx < nW * 64; idx += 256)
        KVs[(idx >> 6) * 65 + (idx & 63)] = kbase[(size_t)jlo * 64 + idx];
    __syncthreads();

    // scores
    const int total = 64 * nW;
    for (int idx = tid; idx < total; idx += 256) {
        const int i = idx / nW;
        const int j = idx - i * nW;
        const int ig = i0 + i;
        const int jg = jlo + j;
        float s;
        if (jg < ig - SPAN || jg > ig + SPAN) {
            s = -3.0e38f;
        } else {
            const float* qr = &Qs[i * 65];
            const float* kr = &KVs[j * 65];
            float acc = 0.f;
#pragma unroll
            for (int kk = 0; kk < 64; kk++) acc += qr[kk] * kr[kk];
            s = acc * 0.125f;
        }
        Ss[i * 321 + j] = s;
    }
    __syncthreads();

    // softmax per row (warp per row) + write attn band
    const int warp = tid >> 5, lane = tid & 31;
    for (int i = warp; i < 64; i += 8) {
        float m = -3.0e38f;
        for (int j = lane; j < nW; j += 32) m = fmaxf(m, Ss[i * 321 + j]);
#pragma unroll
        for (int o = 16; o; o >>= 1) m = fmaxf(m, __shfl_xor_sync(~0u, m, o));
        float sum = 0.f;
        for (int j = lane; j < nW; j += 32) {
            float e = __expf(Ss[i * 321 + j] - m);
            Ss[i * 321 + j] = e;
            sum += e;
        }
#pragma unroll
        for (int o = 16; o; o >>= 1) sum += __shfl_xor_sync(~0u, sum, o);
        const float inv = 1.0f / sum;
        float* arow = attn_out + ((size_t)(h * Bb + b) * L + (i0 + i)) * L;
        for (int j = lane; j < nW; j += 32) {
            float p = Ss[i * 321 + j] * inv;
            Ss[i * 321 + j] = p;
            if (write_attn) arow[jlo + j] = p;
        }
    }
    __syncthreads();

    // overwrite K smem with V window
    for (int idx = tid; idx < nW * 64; idx += 256)
        KVs[(idx >> 6) * 65 + (idx & 63)] = vbase[(size_t)jlo * 64 + idx];
    __syncthreads();

    // out = P @ V  -> ctx[(ig*B+b)*1024 + h*64 + v]
    for (int idx = tid; idx < 64 * 64; idx += 256) {
        const int i = idx >> 6;
        const int vcol = idx & 63;
        float acc = 0.f;
        for (int j = 0; j < nW; j++) acc += Ss[i * 321 + j] * KVs[j * 65 + vcol];
        g_ctx[((size_t)(i0 + i) * Bb + b) * Dd + h * 64 + vcol] = acc;
    }
}

// ---------------- layernorm ----------------
__global__ __launch_bounds__(256) void ln_kernel(const float* __restrict__ yp,
                                                 const float* __restrict__ gamma,
                                                 const float* __restrict__ beta,
                                                 float* __restrict__ out)
{
    const int r = blockIdx.x;
    const int tid = threadIdx.x;
    const float* row = yp + (size_t)r * Dd;
    float v[4];
    float s = 0.f, sq = 0.f;
#pragma unroll
    for (int u = 0; u < 4; u++) {
        v[u] = row[tid + 256 * u];
        s += v[u];
        sq += v[u] * v[u];
    }
    __shared__ float rs[8], rq[8];
#pragma unroll
    for (int o = 16; o; o >>= 1) {
        s += __shfl_xor_sync(~0u, s, o);
        sq += __shfl_xor_sync(~0u, sq, o);
    }
    if ((tid & 31) == 0) { rs[tid >> 5] = s; rq[tid >> 5] = sq; }
    __syncthreads();
    if (tid < 32) {
        s = (tid < 8) ? rs[tid] : 0.f;
        sq = (tid < 8) ? rq[tid] : 0.f;
#pragma unroll
        for (int o = 4; o; o >>= 1) {
            s += __shfl_xor_sync(~0u, s, o);
            sq += __shfl_xor_sync(~0u, sq, o);
        }
        if (tid == 0) {
            float mean = s * (1.0f / Dd);
            float var = sq * (1.0f / Dd) - mean * mean;
            rs[0] = mean;
            rq[0] = rsqrtf(var + LN_EPS);
        }
    }
    __syncthreads();
    const float mean = rs[0], inv = rq[0];
#pragma unroll
    for (int u = 0; u < 4; u++) {
        const int c = tid + 256 * u;
        out[(size_t)r * Dd + c] = (v[u] - mean) * inv * gamma[c] + beta[c];
    }
}

// ---------------- launch ----------------
extern "C" void kernel_launch(void* const* d_in, const int* in_sizes, int n_in,
                              void* d_out, int out_size)
{
    const float* query = (const float*)d_in[0];
    const float* key   = (const float*)d_in[1];
    const float* value = (const float*)d_in[2];
    const float* Wq  = (const float*)d_in[3];
    const float* bq  = (const float*)d_in[4];
    const float* Wk  = (const float*)d_in[5];
    const float* bk  = (const float*)d_in[6];
    const float* Wv  = (const float*)d_in[7];
    const float* bv  = (const float*)d_in[8];
    const float* Wfc = (const float*)d_in[9];
    const float* bfc = (const float*)d_in[10];
    const float* gamma = (const float*)d_in[11];
    const float* beta  = (const float*)d_in[12];

    float* out_y = (float*)d_out;
    const int has_attn = ((size_t)out_size >= LBD + ATTN_ELEMS) ? 1 : 0;
    float* out_attn = out_y + LBD;

    float *pq, *pk, *pv, *pctx, *pyp;
    cudaGetSymbolAddress((void**)&pq, g_q);
    cudaGetSymbolAddress((void**)&pk, g_k);
    cudaGetSymbolAddress((void**)&pv, g_v);
    cudaGetSymbolAddress((void**)&pctx, g_ctx);
    cudaGetSymbolAddress((void**)&pyp, g_yp);

    if (has_attn)
        cudaMemsetAsync(out_attn, 0, ATTN_ELEMS * sizeof(float));

    dim3 gemm_grid(Dd / 128, MROWS / 128);  // (8, 32)
    sgemm128<0><<<gemm_grid, 256>>>(query, Wq, bq, nullptr, pq, MROWS, Dd, Dd);
    sgemm128<0><<<gemm_grid, 256>>>(key,   Wk, bk, nullptr, pk, MROWS, Dd, Dd);
    sgemm128<0><<<gemm_grid, 256>>>(value, Wv, bv, nullptr, pv, MROWS, Dd, Dd);

    cudaFuncSetAttribute(attn_kernel, cudaFuncAttributeMaxDynamicSharedMemorySize,
                         SMEM_ATTN_BYTES);
    dim3 attn_grid(L / 64, Bb, Hh);  // (32, 2, 16)
    attn_kernel<<<attn_grid, 256, SMEM_ATTN_BYTES>>>(has_attn ? out_attn : out_y,
                                                     has_attn);

    sgemm128<1><<<gemm_grid, 256>>>(pctx, Wfc, bfc, query, pyp, MROWS, Dd, Dd);

    ln_kernel<<<MROWS, 256>>>(pyp, gamma, beta, out_y);
}

// round 3
// speedup vs baseline: 3.4797x; 3.4797x over previous
#include <cuda_runtime.h>
#include <math.h>

#define L 2048
#define Bb 2
#define Dd 1024
#define Hh 16
#define DK 64
#define SPAN 128
#define LN_EPS 1e-5f

#define MROWS (L * Bb)          // 4096
#define LBD ((size_t)L * Bb * Dd)               // 4,194,304
#define ATTN_ELEMS ((size_t)Hh * Bb * L * L)    // 134,217,728

// ---------------- scratch ----------------
__device__ float g_qT[Hh * Bb * DK * L];   // [h][b][k][l]
__device__ float g_kT[Hh * Bb * DK * L];   // [h][b][k][l]
__device__ float g_v [Hh * Bb * L * DK];   // [h][b][l][v]
__device__ float g_ctx[MROWS * Dd];
__device__ float g_yp [MROWS * Dd];

// ---------------- helpers ----------------
__device__ __forceinline__ unsigned f2tf32(float x) {
    unsigned u;
    asm("cvt.rna.tf32.f32 %0, %1;" : "=r"(u) : "f"(x));
    return u;
}

__device__ __forceinline__ void mma_tf32(float c[4],
                                         unsigned a0, unsigned a1, unsigned a2, unsigned a3,
                                         unsigned b0, unsigned b1) {
    asm volatile(
        "mma.sync.aligned.m16n8k8.row.col.f32.tf32.tf32.f32 "
        "{%0,%1,%2,%3},{%4,%5,%6,%7},{%8,%9},{%0,%1,%2,%3};"
        : "+f"(c[0]), "+f"(c[1]), "+f"(c[2]), "+f"(c[3])
        : "r"(a0), "r"(a1), "r"(a2), "r"(a3), "r"(b0), "r"(b1));
}

// ---------------- TF32 tensor-core GEMM: 128x128x32 tiles ----------------
// M=4096, N=1024, K=1024 fixed. 256 threads = 8 warps (2x4), warp tile 64x32.
// MODE 0: V natural permute  out[((h*2+b)*L + l)*64 + k]
// MODE 2: Q/K transposed     out[((h*2+b)*64 + k)*L + l]
// MODE 1: FC: out = acc + bias + resid  (row-major M x N)
#define AS_STRIDE 36
#define BS_STRIDE 136
#define GEMM_BUF (128 * AS_STRIDE + 32 * BS_STRIDE)   // floats per buffer
#define GEMM_SMEM_BYTES (2 * GEMM_BUF * 4)

template <int MODE>
__global__ __launch_bounds__(256) void mma_gemm(
    const float* __restrict__ A, const float* __restrict__ B,
    const float* __restrict__ bias, const float* __restrict__ resid,
    float* __restrict__ out)
{
    const int K = 1024, N = 1024;
    extern __shared__ float sm[];

    const int tid = threadIdx.x;
    const int lane = tid & 31;
    const int warp = tid >> 5;
    const int wm = warp >> 2;    // 0..1
    const int wn = warp & 3;     // 0..3
    const int bm = blockIdx.y * 128;
    const int bn = blockIdx.x * 128;

    // gmem load mapping
    const int ar = tid >> 3;          // 0..31 (A row within tile, +32 steps)
    const int ak = (tid & 7) * 4;     // A col (k) float4
    const int br = tid >> 5;          // 0..7  (B row k, +8 steps)
    const int bc = (tid & 31) * 4;    // B col float4

    float acc[4][4][4];
#pragma unroll
    for (int i = 0; i < 4; i++)
#pragma unroll
        for (int j = 0; j < 4; j++)
#pragma unroll
            for (int e = 0; e < 4; e++) acc[i][j][e] = 0.f;

    float4 pa[4], pb[4];

    auto gload = [&](int kt) {
#pragma unroll
        for (int i = 0; i < 4; i++)
            pa[i] = *(const float4*)(A + (size_t)(bm + ar + 32 * i) * K + kt * 32 + ak);
#pragma unroll
        for (int i = 0; i < 4; i++)
            pb[i] = *(const float4*)(B + (size_t)(kt * 32 + br + 8 * i) * N + bn + bc);
    };
    auto sstore = [&](int buf) {
        float* As = sm + buf * GEMM_BUF;
        float* Bs = As + 128 * AS_STRIDE;
#pragma unroll
        for (int i = 0; i < 4; i++) {
            float4 w;
            w.x = __uint_as_float(f2tf32(pa[i].x));
            w.y = __uint_as_float(f2tf32(pa[i].y));
            w.z = __uint_as_float(f2tf32(pa[i].z));
            w.w = __uint_as_float(f2tf32(pa[i].w));
            *(float4*)&As[(ar + 32 * i) * AS_STRIDE + ak] = w;
        }
#pragma unroll
        for (int i = 0; i < 4; i++) {
            float4 w;
            w.x = __uint_as_float(f2tf32(pb[i].x));
            w.y = __uint_as_float(f2tf32(pb[i].y));
            w.z = __uint_as_float(f2tf32(pb[i].z));
            w.w = __uint_as_float(f2tf32(pb[i].w));
            *(float4*)&Bs[(br + 8 * i) * BS_STRIDE + bc] = w;
        }
    };

    gload(0);
    sstore(0);
    __syncthreads();

    for (int kt = 0; kt < 32; kt++) {
        const int cur = kt & 1;
        if (kt < 31) gload(kt + 1);

        const float* As = sm + cur * GEMM_BUF;
        const float* Bs = As + 128 * AS_STRIDE;
#pragma unroll
        for (int k8 = 0; k8 < 32; k8 += 8) {
            unsigned af[4][4], bf[4][2];
#pragma unroll
            for (int mt = 0; mt < 4; mt++) {
                const int r = wm * 64 + mt * 16 + (lane >> 2);
                const int kc = k8 + (lane & 3);
                af[mt][0] = __float_as_uint(As[r * AS_STRIDE + kc]);
                af[mt][1] = __float_as_uint(As[(r + 8) * AS_STRIDE + kc]);
                af[mt][2] = __float_as_uint(As[r * AS_STRIDE + kc + 4]);
                af[mt][3] = __float_as_uint(As[(r + 8) * AS_STRIDE + kc + 4]);
            }
#pragma unroll
            for (int nt = 0; nt < 4; nt++) {
                const int cc = wn * 32 + nt * 8 + (lane >> 2);
                bf[nt][0] = __float_as_uint(Bs[(k8 + (lane & 3)) * BS_STRIDE + cc]);
                bf[nt][1] = __float_as_uint(Bs[(k8 + (lane & 3) + 4) * BS_STRIDE + cc]);
            }
#pragma unroll
            for (int mt = 0; mt < 4; mt++)
#pragma unroll
                for (int nt = 0; nt < 4; nt++)
                    mma_tf32(acc[mt][nt], af[mt][0], af[mt][1], af[mt][2], af[mt][3],
                             bf[nt][0], bf[nt][1]);
        }

        if (kt < 31) {
            sstore(1 - cur);
            __syncthreads();
        }
    }

    // epilogue
#pragma unroll
    for (int mt = 0; mt < 4; mt++) {
#pragma unroll
        for (int nt = 0; nt < 4; nt++) {
            const int row0 = bm + wm * 64 + mt * 16 + (lane >> 2);
            const int col0 = bn + wn * 32 + nt * 8 + (lane & 3) * 2;
#pragma unroll
            for (int half = 0; half < 2; half++) {
                const int m = row0 + half * 8;
#pragma unroll
                for (int e = 0; e < 2; e++) {
                    const int n = col0 + e;
                    float val = acc[mt][nt][half * 2 + e] + bias[n];
                    if (MODE == 0) {
                        const int l = m >> 1, b = m & 1, h = n >> 6, k = n & 63;
                        out[(((size_t)(h * Bb + b) * L + l) * 64) + k] = val;
                    } else if (MODE == 2) {
                        const int l = m >> 1, b = m & 1, h = n >> 6, k = n & 63;
                        out[(((size_t)(h * Bb + b) * 64 + k) * L) + l] = val;
                    } else {
                        val += resid[(size_t)m * N + n];
                        out[(size_t)m * N + n] = val;
                    }
                }
            }
        }
    }
}

// ---------------- banded attention: register-tiled, 64 q rows/CTA ----------------
// smem: Qs[64][68] (k,i) | KVs[64][68] (K: k,j ; V: j,v) | Ps[64][68] (i,j)
#define AT_STRIDE 68
#define ATTN_SMEM_BYTES (3 * 64 * AT_STRIDE * 4)

__global__ __launch_bounds__(256, 2) void attn_kernel(float* __restrict__ attn_out,
                                                      int write_attn)
{
    extern __shared__ float sm[];
    float* Qs  = sm;
    float* KVs = sm + 64 * AT_STRIDE;
    float* Ps  = sm + 2 * 64 * AT_STRIDE;

    const int tid = threadIdx.x;
    const int tx = tid & 15;
    const int ty = tid >> 4;
    const int h = blockIdx.z;
    const int b = blockIdx.y;
    const int hb = h * Bb + b;
    const int i0 = blockIdx.x * 64;

    const float* qT = g_qT + (size_t)hb * 64 * L;
    const float* kT = g_kT + (size_t)hb * 64 * L;
    const float* vb = g_v + (size_t)hb * L * 64;

    // load Q tile (transposed source: rows = k, cols = l)
    {
        const int r = tid >> 2;
        const int c0 = (tid & 3) * 4;
#pragma unroll
        for (int it = 0; it < 4; it++) {
            const int c = c0 + it * 16;
            *(float4*)&Qs[r * AT_STRIDE + c] = *(const float4*)(qT + (size_t)r * L + i0 + c);
        }
    }

    float s[5][4][4];
#pragma unroll
    for (int t = 0; t < 5; t++)
#pragma unroll
        for (int i = 0; i < 4; i++)
#pragma unroll
            for (int j = 0; j < 4; j++) s[t][i][j] = -1e30f;

    // ---- score tiles ----
#pragma unroll
    for (int t = 0; t < 5; t++) {
        const int j0 = i0 - SPAN + t * 64;
        if (j0 < 0 || j0 >= L) continue;

        __syncthreads();
        // load K tile rows=k cols=j
        {
            const int r = tid >> 2;
            const int c0 = (tid & 3) * 4;
#pragma unroll
            for (int it = 0; it < 4; it++) {
                const int c = c0 + it * 16;
                *(float4*)&KVs[r * AT_STRIDE + c] = *(const float4*)(kT + (size_t)r * L + j0 + c);
            }
        }
        __syncthreads();

        float a4[4][4];
#pragma unroll
        for (int i = 0; i < 4; i++)
#pragma unroll
            for (int j = 0; j < 4; j++) a4[i][j] = 0.f;

#pragma unroll 8
        for (int kk = 0; kk < 64; kk++) {
            float4 qa = *(float4*)&Qs[kk * AT_STRIDE + ty * 4];
            float4 kb = *(float4*)&KVs[kk * AT_STRIDE + tx * 4];
            float av[4] = {qa.x, qa.y, qa.z, qa.w};
            float bv[4] = {kb.x, kb.y, kb.z, kb.w};
#pragma unroll
            for (int i = 0; i < 4; i++)
#pragma unroll
                for (int j = 0; j < 4; j++) a4[i][j] += av[i] * bv[j];
        }

#pragma unroll
        for (int i = 0; i < 4; i++) {
            const int ig = i0 + ty * 4 + i;
#pragma unroll
            for (int j = 0; j < 4; j++) {
                const int jg = j0 + tx * 4 + j;
                const int d = jg - ig;
                s[t][i][j] = (d >= -SPAN && d <= SPAN) ? a4[i][j] * 0.125f : -1e30f;
            }
        }
    }

    // ---- softmax over registers (rows owned by 16-lane half-warps) ----
    float inv_l[4];
#pragma unroll
    for (int i = 0; i < 4; i++) {
        float m = -1e30f;
#pragma unroll
        for (int t = 0; t < 5; t++)
#pragma unroll
            for (int j = 0; j < 4; j++) m = fmaxf(m, s[t][i][j]);
#pragma unroll
        for (int o = 1; o < 16; o <<= 1) m = fmaxf(m, __shfl_xor_sync(~0u, m, o));
        float l = 0.f;
#pragma unroll
        for (int t = 0; t < 5; t++)
#pragma unroll
            for (int j = 0; j < 4; j++) {
                float e = __expf(s[t][i][j] - m);
                s[t][i][j] = e;
                l += e;
            }
#pragma unroll
        for (int o = 1; o < 16; o <<= 1) l += __shfl_xor_sync(~0u, l, o);
        inv_l[i] = 1.0f / l;
    }
#pragma unroll
    for (int t = 0; t < 5; t++)
#pragma unroll
        for (int i = 0; i < 4; i++)
#pragma unroll
            for (int j = 0; j < 4; j++) s[t][i][j] *= inv_l[i];

    // ---- write attn band ----
    if (write_attn) {
#pragma unroll
        for (int t = 0; t < 5; t++) {
            const int j0 = i0 - SPAN + t * 64;
            if (j0 < 0 || j0 >= L) continue;
#pragma unroll
            for (int i = 0; i < 4; i++) {
                const int ig = i0 + ty * 4 + i;
                float4 w = make_float4(s[t][i][0], s[t][i][1], s[t][i][2], s[t][i][3]);
                *(float4*)(attn_out + ((size_t)hb * L + ig) * L + j0 + tx * 4) = w;
            }
        }
    }

    // ---- PV ----
    float o4[4][4];
#pragma unroll
    for (int i = 0; i < 4; i++)
#pragma unroll
        for (int j = 0; j < 4; j++) o4[i][j] = 0.f;

#pragma unroll
    for (int t = 0; t < 5; t++) {
        const int j0 = i0 - SPAN + t * 64;
        if (j0 < 0 || j0 >= L) continue;

        __syncthreads();
        // load V tile rows=j cols=v (natural layout)
        {
            const int r = tid >> 2;
            const int c0 = (tid & 3) * 4;
#pragma unroll
            for (int it = 0; it < 4; it++) {
                const int c = c0 + it * 16;
                *(float4*)&KVs[r * AT_STRIDE + c] = *(const float4*)(vb + (size_t)(j0 + r) * 64 + c);
            }
        }
        // store P tile [i][j]
#pragma unroll
        for (int i = 0; i < 4; i++) {
            float4 w = make_float4(s[t][i][0], s[t][i][1], s[t][i][2], s[t][i][3]);
            *(float4*)&Ps[(ty * 4 + i) * AT_STRIDE + tx * 4] = w;
        }
        __syncthreads();

#pragma unroll 8
        for (int kk = 0; kk < 64; kk++) {
            float av[4];
#pragma unroll
            for (int i = 0; i < 4; i++) av[i] = Ps[(ty * 4 + i) * AT_STRIDE + kk];
            float4 vbv = *(float4*)&KVs[kk * AT_STRIDE + tx * 4];
            float bv[4] = {vbv.x, vbv.y, vbv.z, vbv.w};
#pragma unroll
            for (int i = 0; i < 4; i++)
#pragma unroll
                for (int j = 0; j < 4; j++) o4[i][j] += av[i] * bv[j];
        }
    }

    // write ctx: [(l*B + b)*1024 + h*64 + v]
#pragma unroll
    for (int i = 0; i < 4; i++) {
        const int ig = i0 + ty * 4 + i;
        float4 w = make_float4(o4[i][0], o4[i][1], o4[i][2], o4[i][3]);
        *(float4*)(g_ctx + ((size_t)ig * Bb + b) * Dd + h * 64 + tx * 4) = w;
    }
}

// ---------------- layernorm ----------------
__global__ __launch_bounds__(256) void ln_kernel(const float* __restrict__ yp,
                                                 const float* __restrict__ gamma,
                                                 const float* __restrict__ beta,
                                                 float* __restrict__ out)
{
    const int r = blockIdx.x;
    const int tid = threadIdx.x;
    const float* row = yp + (size_t)r * Dd;
    float v[4];
    float sum = 0.f, sq = 0.f;
#pragma unroll
    for (int u = 0; u < 4; u++) {
        v[u] = row[tid + 256 * u];
        sum += v[u];
        sq += v[u] * v[u];
    }
    __shared__ float rs[8], rq[8];
#pragma unroll
    for (int o = 16; o; o >>= 1) {
        sum += __shfl_xor_sync(~0u, sum, o);
        sq  += __shfl_xor_sync(~0u, sq, o);
    }
    if ((tid & 31) == 0) { rs[tid >> 5] = sum; rq[tid >> 5] = sq; }
    __syncthreads();
    if (tid < 32) {
        sum = (tid < 8) ? rs[tid] : 0.f;
        sq  = (tid < 8) ? rq[tid] : 0.f;
#pragma unroll
        for (int o = 4; o; o >>= 1) {
            sum += __shfl_xor_sync(~0u, sum, o);
            sq  += __shfl_xor_sync(~0u, sq, o);
        }
        if (tid == 0) {
            float mean = sum * (1.0f / Dd);
            float var = sq * (1.0f / Dd) - mean * mean;
            rs[0] = mean;
            rq[0] = rsqrtf(var + LN_EPS);
        }
    }
    __syncthreads();
    const float mean = rs[0], inv = rq[0];
#pragma unroll
    for (int u = 0; u < 4; u++) {
        const int c = tid + 256 * u;
        out[(size_t)r * Dd + c] = (v[u] - mean) * inv * gamma[c] + beta[c];
    }
}

// ---------------- launch ----------------
extern "C" void kernel_launch(void* const* d_in, const int* in_sizes, int n_in,
                              void* d_out, int out_size)
{
    const float* query = (const float*)d_in[0];
    const float* key   = (const float*)d_in[1];
    const float* value = (const float*)d_in[2];
    const float* Wq  = (const float*)d_in[3];
    const float* bq  = (const float*)d_in[4];
    const float* Wk  = (const float*)d_in[5];
    const float* bk  = (const float*)d_in[6];
    const float* Wv  = (const float*)d_in[7];
    const float* bv  = (const float*)d_in[8];
    const float* Wfc = (const float*)d_in[9];
    const float* bfc = (const float*)d_in[10];
    const float* gamma = (const float*)d_in[11];
    const float* beta  = (const float*)d_in[12];

    float* out_y = (float*)d_out;
    const int has_attn = ((size_t)out_size >= LBD + ATTN_ELEMS) ? 1 : 0;
    float* out_attn = out_y + LBD;

    float *pqT, *pkT, *pv, *pctx, *pyp;
    cudaGetSymbolAddress((void**)&pqT, g_qT);
    cudaGetSymbolAddress((void**)&pkT, g_kT);
    cudaGetSymbolAddress((void**)&pv,  g_v);
    cudaGetSymbolAddress((void**)&pctx, g_ctx);
    cudaGetSymbolAddress((void**)&pyp, g_yp);

    cudaFuncSetAttribute(mma_gemm<0>, cudaFuncAttributeMaxDynamicSharedMemorySize, GEMM_SMEM_BYTES);
    cudaFuncSetAttribute(mma_gemm<1>, cudaFuncAttributeMaxDynamicSharedMemorySize, GEMM_SMEM_BYTES);
    cudaFuncSetAttribute(mma_gemm<2>, cudaFuncAttributeMaxDynamicSharedMemorySize, GEMM_SMEM_BYTES);
    cudaFuncSetAttribute(attn_kernel, cudaFuncAttributeMaxDynamicSharedMemorySize, ATTN_SMEM_BYTES);

    if (has_attn)
        cudaMemsetAsync(out_attn, 0, ATTN_ELEMS * sizeof(float));

    dim3 gemm_grid(Dd / 128, MROWS / 128);  // (8, 32)
    mma_gemm<2><<<gemm_grid, 256, GEMM_SMEM_BYTES>>>(query, Wq, bq, nullptr, pqT);
    mma_gemm<2><<<gemm_grid, 256, GEMM_SMEM_BYTES>>>(key,   Wk, bk, nullptr, pkT);
    mma_gemm<0><<<gemm_grid, 256, GEMM_SMEM_BYTES>>>(value, Wv, bv, nullptr, pv);

    dim3 attn_grid(L / 64, Bb, Hh);  // (32, 2, 16)
    attn_kernel<<<attn_grid, 256, ATTN_SMEM_BYTES>>>(has_attn ? out_attn : out_y, has_attn);

    mma_gemm<1><<<gemm_grid, 256, GEMM_SMEM_BYTES>>>(pctx, Wfc, bfc, query, pyp);

    ln_kernel<<<MROWS, 256>>>(pyp, gamma, beta, out_y);
}

// round 5
// speedup vs baseline: 3.7296x; 1.0718x over previous
#include <cuda_runtime.h>
#include <math.h>
#include <stdint.h>

#define L 2048
#define Bb 2
#define Dd 1024
#define Hh 16
#define SPAN 128
#define LN_EPS 1e-5f

#define MROWS (L * Bb)                          // 4096
#define LBD ((size_t)L * Bb * Dd)               // 4,194,304
#define ATTN_ELEMS ((size_t)Hh * Bb * L * L)    // 134,217,728

// ---------------- scratch ----------------
__device__ float g_q [Hh * Bb * L * 64];    // [h][b][l][k]  natural
__device__ float g_k [Hh * Bb * L * 64];    // [h][b][l][k]  natural
__device__ float g_vT[Hh * Bb * 64 * L];    // [h][b][v][l]  transposed
__device__ float g_ctx[MROWS * Dd];
__device__ float g_yp [MROWS * Dd];

// ---------------- helpers ----------------
__device__ __forceinline__ unsigned f2tf32(float x) {
    unsigned u;
    asm("cvt.rna.tf32.f32 %0, %1;" : "=r"(u) : "f"(x));
    return u;
}
__device__ __forceinline__ float rnaf(float x) { return __uint_as_float(f2tf32(x)); }

__device__ __forceinline__ void mma_tf32(float c[4],
                                         unsigned a0, unsigned a1, unsigned a2, unsigned a3,
                                         unsigned b0, unsigned b1) {
    asm volatile(
        "mma.sync.aligned.m16n8k8.row.col.f32.tf32.tf32.f32 "
        "{%0,%1,%2,%3},{%4,%5,%6,%7},{%8,%9},{%0,%1,%2,%3};"
        : "+f"(c[0]), "+f"(c[1]), "+f"(c[2]), "+f"(c[3])
        : "r"(a0), "r"(a1), "r"(a2), "r"(a3), "r"(b0), "r"(b1));
}

// ---------------- TF32 tensor-core GEMM (R3): 128x128x32 tiles ----------------
// MODE 0: natural permute  out[((h*2+b)*L + l)*64 + k]   (Q, K)
// MODE 2: transposed       out[((h*2+b)*64 + k)*L + l]   (V)
// MODE 1: FC               out = acc + bias + resid
#define AS_STRIDE 36
#define BS_STRIDE 136
#define GEMM_BUF (128 * AS_STRIDE + 32 * BS_STRIDE)
#define GEMM_SMEM_BYTES (2 * GEMM_BUF * 4)

template <int MODE>
__global__ __launch_bounds__(256) void mma_gemm(
    const float* __restrict__ A, const float* __restrict__ B,
    const float* __restrict__ bias, const float* __restrict__ resid,
    float* __restrict__ out)
{
    const int K = 1024, N = 1024;
    extern __shared__ float sm[];

    const int tid = threadIdx.x;
    const int lane = tid & 31;
    const int warp = tid >> 5;
    const int wm = warp >> 2;
    const int wn = warp & 3;
    const int bm = blockIdx.y * 128;
    const int bn = blockIdx.x * 128;

    const int ar = tid >> 3;
    const int ak = (tid & 7) * 4;
    const int br = tid >> 5;
    const int bc = (tid & 31) * 4;

    float acc[4][4][4];
#pragma unroll
    for (int i = 0; i < 4; i++)
#pragma unroll
        for (int j = 0; j < 4; j++)
#pragma unroll
            for (int e = 0; e < 4; e++) acc[i][j][e] = 0.f;

    float4 pa[4], pb[4];

    auto gload = [&](int kt) {
#pragma unroll
        for (int i = 0; i < 4; i++)
            pa[i] = *(const float4*)(A + (size_t)(bm + ar + 32 * i) * K + kt * 32 + ak);
#pragma unroll
        for (int i = 0; i < 4; i++)
            pb[i] = *(const float4*)(B + (size_t)(kt * 32 + br + 8 * i) * N + bn + bc);
    };
    auto sstore = [&](int buf) {
        float* As = sm + buf * GEMM_BUF;
        float* Bs = As + 128 * AS_STRIDE;
#pragma unroll
        for (int i = 0; i < 4; i++) {
            float4 w;
            w.x = __uint_as_float(f2tf32(pa[i].x));
            w.y = __uint_as_float(f2tf32(pa[i].y));
            w.z = __uint_as_float(f2tf32(pa[i].z));
            w.w = __uint_as_float(f2tf32(pa[i].w));
            *(float4*)&As[(ar + 32 * i) * AS_STRIDE + ak] = w;
        }
#pragma unroll
        for (int i = 0; i < 4; i++) {
            float4 w;
            w.x = __uint_as_float(f2tf32(pb[i].x));
            w.y = __uint_as_float(f2tf32(pb[i].y));
            w.z = __uint_as_float(f2tf32(pb[i].z));
            w.w = __uint_as_float(f2tf32(pb[i].w));
            *(float4*)&Bs[(br + 8 * i) * BS_STRIDE + bc] = w;
        }
    };

    gload(0);
    sstore(0);
    __syncthreads();

    for (int kt = 0; kt < 32; kt++) {
        const int cur = kt & 1;
        if (kt < 31) gload(kt + 1);

        const float* As = sm + cur * GEMM_BUF;
        const float* Bs = As + 128 * AS_STRIDE;
#pragma unroll
        for (int k8 = 0; k8 < 32; k8 += 8) {
            unsigned af[4][4], bf[4][2];
#pragma unroll
            for (int mt = 0; mt < 4; mt++) {
                const int r = wm * 64 + mt * 16 + (lane >> 2);
                const int kc = k8 + (lane & 3);
                af[mt][0] = __float_as_uint(As[r * AS_STRIDE + kc]);
                af[mt][1] = __float_as_uint(As[(r + 8) * AS_STRIDE + kc]);
                af[mt][2] = __float_as_uint(As[r * AS_STRIDE + kc + 4]);
                af[mt][3] = __float_as_uint(As[(r + 8) * AS_STRIDE + kc + 4]);
            }
#pragma unroll
            for (int nt = 0; nt < 4; nt++) {
                const int cc = wn * 32 + nt * 8 + (lane >> 2);
                bf[nt][0] = __float_as_uint(Bs[(k8 + (lane & 3)) * BS_STRIDE + cc]);
                bf[nt][1] = __float_as_uint(Bs[(k8 + (lane & 3) + 4) * BS_STRIDE + cc]);
            }
#pragma unroll
            for (int mt = 0; mt < 4; mt++)
#pragma unroll
                for (int nt = 0; nt < 4; nt++)
                    mma_tf32(acc[mt][nt], af[mt][0], af[mt][1], af[mt][2], af[mt][3],
                             bf[nt][0], bf[nt][1]);
        }

        if (kt < 31) {
            sstore(1 - cur);
            __syncthreads();
        }
    }

#pragma unroll
    for (int mt = 0; mt < 4; mt++) {
#pragma unroll
        for (int nt = 0; nt < 4; nt++) {
            const int row0 = bm + wm * 64 + mt * 16 + (lane >> 2);
            const int col0 = bn + wn * 32 + nt * 8 + (lane & 3) * 2;
#pragma unroll
            for (int half = 0; half < 2; half++) {
                const int m = row0 + half * 8;
#pragma unroll
                for (int e = 0; e < 2; e++) {
                    const int n = col0 + e;
                    float val = acc[mt][nt][half * 2 + e] + bias[n];
                    if (MODE == 0) {
                        const int l = m >> 1, b = m & 1, h = n >> 6, k = n & 63;
                        out[(((size_t)(h * Bb + b) * L + l) * 64) + k] = val;
                    } else if (MODE == 2) {
                        const int l = m >> 1, b = m & 1, h = n >> 6, k = n & 63;
                        out[(((size_t)(h * Bb + b) * 64 + k) * L) + l] = val;
                    } else {
                        val += resid[(size_t)m * N + n];
                        out[(size_t)m * N + n] = val;
                    }
                }
            }
        }
    }
}

// ---------------- banded attention via mma.sync tf32 ----------------
// CTA: 64 q rows, 5 j-tiles of 64, 8 warps: wm=wid&3 (16 rows), wn=wid>>2 (32 cols)
// QK^T: 3-mma tf32 split (fp32-faithful). PV: 1-mma tf32 (P,V rna-rounded).
#define ATS 68

__global__ __launch_bounds__(256) void attn_mma(float* __restrict__ attn_out,
                                                int write_attn)
{
    __shared__ float Abuf[64 * ATS];   // Qs (phase 1), Ps (phase 2)
    __shared__ float Bbuf[64 * ATS];   // Ks (phase 1), VTs (phase 2)
    __shared__ float Rm[2][64], Rs[2][64];

    const int tid = threadIdx.x;
    const int lane = tid & 31;
    const int wid = tid >> 5;
    const int wm = wid & 3;
    const int wn = wid >> 2;
    const int qr = lane >> 2;      // quad row
    const int ql = lane & 3;       // quad lane
    const int h = blockIdx.z;
    const int b = blockIdx.y;
    const int hb = h * Bb + b;
    const int i0 = blockIdx.x * 64;
    const int iLo = i0 + wm * 16, iHi = iLo + 15;

    const float* qb  = g_q  + (size_t)hb * L * 64;
    const float* kb  = g_k  + (size_t)hb * L * 64;
    const float* vTb = g_vT + (size_t)hb * 64 * L;

    // load Q tile natural [i][k]
    {
        const int r = tid >> 2, c0 = (tid & 3) * 4;
#pragma unroll
        for (int it = 0; it < 4; it++)
            *(float4*)&Abuf[r * ATS + c0 + it * 16] =
                *(const float4*)(qb + (size_t)(i0 + r) * 64 + c0 + it * 16);
    }

    float s[5][4][4];
#pragma unroll
    for (int t = 0; t < 5; t++)
#pragma unroll
        for (int nt = 0; nt < 4; nt++)
#pragma unroll
            for (int e = 0; e < 4; e++) s[t][nt][e] = 0.f;

    // ---------- phase 1: scores ----------
#pragma unroll
    for (int t = 0; t < 5; t++) {
        const int j0 = i0 - SPAN + t * 64;
        if (j0 < 0 || j0 >= L) continue;

        __syncthreads();
        {
            const int r = tid >> 2, c0 = (tid & 3) * 4;
#pragma unroll
            for (int it = 0; it < 4; it++)
                *(float4*)&Bbuf[r * ATS + c0 + it * 16] =
                    *(const float4*)(kb + (size_t)(j0 + r) * 64 + c0 + it * 16);
        }
        __syncthreads();

        bool ok[4];
#pragma unroll
        for (int nt = 0; nt < 4; nt++) {
            const int jlo = j0 + wn * 32 + nt * 8;
            ok[nt] = !((jlo + 7 < iLo - SPAN) || (jlo > iHi + SPAN));
        }

#pragma unroll
        for (int k8 = 0; k8 < 8; k8++) {
            const int kc = k8 * 8 + ql;
            const int ra = (wm * 16 + qr) * ATS;
            const float a0 = Abuf[ra + kc];
            const float a1 = Abuf[ra + 8 * ATS + kc];
            const float a2 = Abuf[ra + kc + 4];
            const float a3 = Abuf[ra + 8 * ATS + kc + 4];
            unsigned ah[4] = {f2tf32(a0), f2tf32(a1), f2tf32(a2), f2tf32(a3)};
            unsigned al[4] = {f2tf32(a0 - __uint_as_float(ah[0])),
                              f2tf32(a1 - __uint_as_float(ah[1])),
                              f2tf32(a2 - __uint_as_float(ah[2])),
                              f2tf32(a3 - __uint_as_float(ah[3]))};
            unsigned bh[4][2], bl[4][2];
#pragma unroll
            for (int nt = 0; nt < 4; nt++) {
                if (!ok[nt]) continue;
                const int rb = (wn * 32 + nt * 8 + qr) * ATS;
                const float b0 = Bbuf[rb + kc];
                const float b1 = Bbuf[rb + kc + 4];
                bh[nt][0] = f2tf32(b0);
                bh[nt][1] = f2tf32(b1);
                bl[nt][0] = f2tf32(b0 - __uint_as_float(bh[nt][0]));
                bl[nt][1] = f2tf32(b1 - __uint_as_float(bh[nt][1]));
            }
#pragma unroll
            for (int nt = 0; nt < 4; nt++)
                if (ok[nt]) mma_tf32(s[t][nt], ah[0], ah[1], ah[2], ah[3], bh[nt][0], bh[nt][1]);
#pragma unroll
            for (int nt = 0; nt < 4; nt++)
                if (ok[nt]) mma_tf32(s[t][nt], al[0], al[1], al[2], al[3], bh[nt][0], bh[nt][1]);
#pragma unroll
            for (int nt = 0; nt < 4; nt++)
                if (ok[nt]) mma_tf32(s[t][nt], ah[0], ah[1], ah[2], ah[3], bl[nt][0], bl[nt][1]);
        }
    }

    // scale + band mask
#pragma unroll
    for (int t = 0; t < 5; t++) {
        const int j0 = i0 - SPAN + t * 64;
#pragma unroll
        for (int nt = 0; nt < 4; nt++)
#pragma unroll
            for (int e = 0; e < 4; e++) {
                const int i = i0 + wm * 16 + qr + ((e >= 2) ? 8 : 0);
                const int j = j0 + wn * 32 + nt * 8 + 2 * ql + (e & 1);
                const int d = j - i;
                const bool valid = (j >= 0) && (j < L) && (d >= -SPAN) && (d <= SPAN);
                s[t][nt][e] = valid ? s[t][nt][e] * 0.125f : -1e30f;
            }
    }

    // ---------- softmax ----------
    const int rlo = wm * 16 + qr, rhi = rlo + 8;
    float mlo = -1e30f, mhi = -1e30f;
#pragma unroll
    for (int t = 0; t < 5; t++)
#pragma unroll
        for (int nt = 0; nt < 4; nt++) {
            mlo = fmaxf(mlo, fmaxf(s[t][nt][0], s[t][nt][1]));
            mhi = fmaxf(mhi, fmaxf(s[t][nt][2], s[t][nt][3]));
        }
    mlo = fmaxf(mlo, __shfl_xor_sync(~0u, mlo, 1));
    mlo = fmaxf(mlo, __shfl_xor_sync(~0u, mlo, 2));
    mhi = fmaxf(mhi, __shfl_xor_sync(~0u, mhi, 1));
    mhi = fmaxf(mhi, __shfl_xor_sync(~0u, mhi, 2));
    if (ql == 0) { Rm[wn][rlo] = mlo; Rm[wn][rhi] = mhi; }
    __syncthreads();
    mlo = fmaxf(Rm[0][rlo], Rm[1][rlo]);
    mhi = fmaxf(Rm[0][rhi], Rm[1][rhi]);

    float slo = 0.f, shi = 0.f;
#pragma unroll
    for (int t = 0; t < 5; t++)
#pragma unroll
        for (int nt = 0; nt < 4; nt++) {
            s[t][nt][0] = __expf(s[t][nt][0] - mlo);
            s[t][nt][1] = __expf(s[t][nt][1] - mlo);
            s[t][nt][2] = __expf(s[t][nt][2] - mhi);
            s[t][nt][3] = __expf(s[t][nt][3] - mhi);
            slo += s[t][nt][0] + s[t][nt][1];
            shi += s[t][nt][2] + s[t][nt][3];
        }
    slo += __shfl_xor_sync(~0u, slo, 1);
    slo += __shfl_xor_sync(~0u, slo, 2);
    shi += __shfl_xor_sync(~0u, shi, 1);
    shi += __shfl_xor_sync(~0u, shi, 2);
    if (ql == 0) { Rs[wn][rlo] = slo; Rs[wn][rhi] = shi; }
    __syncthreads();
    const float invlo = 1.0f / (Rs[0][rlo] + Rs[1][rlo]);
    const float invhi = 1.0f / (Rs[0][rhi] + Rs[1][rhi]);
#pragma unroll
    for (int t = 0; t < 5; t++)
#pragma unroll
        for (int nt = 0; nt < 4; nt++) {
            s[t][nt][0] *= invlo;
            s[t][nt][1] *= invlo;
            s[t][nt][2] *= invhi;
            s[t][nt][3] *= invhi;
        }

    // ---------- phase 2: attn write + PV ----------
    float o[4][4];
#pragma unroll
    for (int nt = 0; nt < 4; nt++)
#pragma unroll
        for (int e = 0; e < 4; e++) o[nt][e] = 0.f;

#pragma unroll
    for (int t = 0; t < 5; t++) {
        const int j0 = i0 - SPAN + t * 64;
        if (j0 < 0 || j0 >= L) continue;

        __syncthreads();
        // V^T tile: rows v, cols j (rna-rounded for mma)
        {
            const int r = tid >> 2, c0 = (tid & 3) * 4;
#pragma unroll
            for (int it = 0; it < 4; it++) {
                float4 x = *(const float4*)(vTb + (size_t)r * L + j0 + c0 + it * 16);
                x.x = rnaf(x.x); x.y = rnaf(x.y); x.z = rnaf(x.z); x.w = rnaf(x.w);
                *(float4*)&Bbuf[r * ATS + c0 + it * 16] = x;
            }
        }
        // P tile to smem (rna) + raw attn band write
#pragma unroll
        for (int nt = 0; nt < 4; nt++) {
            const int col = wn * 32 + nt * 8 + 2 * ql;
            Abuf[rlo * ATS + col]     = rnaf(s[t][nt][0]);
            Abuf[rlo * ATS + col + 1] = rnaf(s[t][nt][1]);
            Abuf[rhi * ATS + col]     = rnaf(s[t][nt][2]);
            Abuf[rhi * ATS + col + 1] = rnaf(s[t][nt][3]);
            if (write_attn) {
                const int jg = j0 + col;
                float2 w0 = make_float2(s[t][nt][0], s[t][nt][1]);
                float2 w1 = make_float2(s[t][nt][2], s[t][nt][3]);
                *(float2*)(attn_out + ((size_t)hb * L + (i0 + rlo)) * L + jg) = w0;
                *(float2*)(attn_out + ((size_t)hb * L + (i0 + rhi)) * L + jg) = w1;
            }
        }
        __syncthreads();

#pragma unroll
        for (int k8 = 0; k8 < 8; k8++) {
            const int jb = j0 + k8 * 8;
            if ((jb + 7 < iLo - SPAN) || (jb > iHi + SPAN)) continue;
            const int kc = k8 * 8 + ql;
            const int ra = (wm * 16 + qr) * ATS;
            const unsigned a0 = __float_as_uint(Abuf[ra + kc]);
            const unsigned a1 = __float_as_uint(Abuf[ra + 8 * ATS + kc]);
            const unsigned a2 = __float_as_uint(Abuf[ra + kc + 4]);
            const unsigned a3 = __float_as_uint(Abuf[ra + 8 * ATS + kc + 4]);
#pragma unroll
            for (int nt = 0; nt < 4; nt++) {
                const int rb = (wn * 32 + nt * 8 + qr) * ATS;
                const unsigned b0 = __float_as_uint(Bbuf[rb + kc]);
                const unsigned b1 = __float_as_uint(Bbuf[rb + kc + 4]);
                mma_tf32(o[nt], a0, a1, a2, a3, b0, b1);
            }
        }
    }

    // ctx writes: [(l*B + b)*1024 + h*64 + v]
#pragma unroll
    for (int nt = 0; nt < 4; nt++) {
        const int v = wn * 32 + nt * 8 + 2 * ql;
        *(float2*)(g_ctx + ((size_t)(i0 + rlo) * Bb + b) * Dd + h * 64 + v) =
            make_float2(o[nt][0], o[nt][1]);
        *(float2*)(g_ctx + ((size_t)(i0 + rhi) * Bb + b) * Dd + h * 64 + v) =
            make_float2(o[nt][2], o[nt][3]);
    }
}

// ---------------- layernorm ----------------
__global__ __launch_bounds__(256) void ln_kernel(const float* __restrict__ yp,
                                                 const float* __restrict__ gamma,
                                                 const float* __restrict__ beta,
                                                 float* __restrict__ out)
{
    const int r = blockIdx.x;
    const int tid = threadIdx.x;
    const float* row = yp + (size_t)r * Dd;
    float v[4];
    float sum = 0.f, sq = 0.f;
#pragma unroll
    for (int u = 0; u < 4; u++) {
        v[u] = row[tid + 256 * u];
        sum += v[u];
        sq += v[u] * v[u];
    }
    __shared__ float rs[8], rq[8];
#pragma unroll
    for (int o = 16; o; o >>= 1) {
        sum += __shfl_xor_sync(~0u, sum, o);
        sq  += __shfl_xor_sync(~0u, sq, o);
    }
    if ((tid & 31) == 0) { rs[tid >> 5] = sum; rq[tid >> 5] = sq; }
    __syncthreads();
    if (tid < 32) {
        sum = (tid < 8) ? rs[tid] : 0.f;
        sq  = (tid < 8) ? rq[tid] : 0.f;
#pragma unroll
        for (int o = 4; o; o >>= 1) {
            sum += __shfl_xor_sync(~0u, sum, o);
            sq  += __shfl_xor_sync(~0u, sq, o);
        }
        if (tid == 0) {
            float mean = sum * (1.0f / Dd);
            float var = sq * (1.0f / Dd) - mean * mean;
            rs[0] = mean;
            rq[0] = rsqrtf(var + LN_EPS);
        }
    }
    __syncthreads();
    const float mean = rs[0], inv = rq[0];
#pragma unroll
    for (int u = 0; u < 4; u++) {
        const int c = tid + 256 * u;
        out[(size_t)r * Dd + c] = (v[u] - mean) * inv * gamma[c] + beta[c];
    }
}

// ---------------- launch ----------------
extern "C" void kernel_launch(void* const* d_in, const int* in_sizes, int n_in,
                              void* d_out, int out_size)
{
    const float* query = (const float*)d_in[0];
    const float* key   = (const float*)d_in[1];
    const float* value = (const float*)d_in[2];
    const float* Wq  = (const float*)d_in[3];
    const float* bq  = (const float*)d_in[4];
    const float* Wk  = (const float*)d_in[5];
    const float* bk  = (const float*)d_in[6];
    const float* Wv  = (const float*)d_in[7];
    const float* bv  = (const float*)d_in[8];
    const float* Wfc = (const float*)d_in[9];
    const float* bfc = (const float*)d_in[10];
    const float* gamma = (const float*)d_in[11];
    const float* beta  = (const float*)d_in[12];

    float* out_y = (float*)d_out;
    const int has_attn = ((size_t)out_size >= LBD + ATTN_ELEMS) ? 1 : 0;
    float* out_attn = out_y + LBD;

    float *pq, *pk, *pvT, *pctx, *pyp;
    cudaGetSymbolAddress((void**)&pq, g_q);
    cudaGetSymbolAddress((void**)&pk, g_k);
    cudaGetSymbolAddress((void**)&pvT, g_vT);
    cudaGetSymbolAddress((void**)&pctx, g_ctx);
    cudaGetSymbolAddress((void**)&pyp, g_yp);

    cudaFuncSetAttribute(mma_gemm<0>, cudaFuncAttributeMaxDynamicSharedMemorySize, GEMM_SMEM_BYTES);
    cudaFuncSetAttribute(mma_gemm<1>, cudaFuncAttributeMaxDynamicSharedMemorySize, GEMM_SMEM_BYTES);
    cudaFuncSetAttribute(mma_gemm<2>, cudaFuncAttributeMaxDynamicSharedMemorySize, GEMM_SMEM_BYTES);

    // fork the big attn-zero memset onto a side stream so it overlaps the
    // three projection GEMMs; join before attn_mma writes the band.
    cudaStream_t s2 = 0;
    cudaEvent_t e1 = 0, e2 = 0;
    if (has_attn) {
        cudaStreamCreateWithFlags(&s2, cudaStreamNonBlocking);
        cudaEventCreateWithFlags(&e1, cudaEventDisableTiming);
        cudaEventCreateWithFlags(&e2, cudaEventDisableTiming);
        cudaEventRecord(e1, 0);
        cudaStreamWaitEvent(s2, e1, 0);
        cudaMemsetAsync(out_attn, 0, ATTN_ELEMS * sizeof(float), s2);
        cudaEventRecord(e2, s2);
    }

    dim3 gemm_grid(Dd / 128, MROWS / 128);  // (8, 32)
    mma_gemm<0><<<gemm_grid, 256, GEMM_SMEM_BYTES>>>(query, Wq, bq, nullptr, pq);
    mma_gemm<0><<<gemm_grid, 256, GEMM_SMEM_BYTES>>>(key,   Wk, bk, nullptr, pk);
    mma_gemm<2><<<gemm_grid, 256, GEMM_SMEM_BYTES>>>(value, Wv, bv, nullptr, pvT);

    if (has_attn) cudaStreamWaitEvent(0, e2, 0);

    dim3 attn_grid(L / 64, Bb, Hh);  // (32, 2, 16)
    attn_mma<<<attn_grid, 256>>>(has_attn ? out_attn : out_y, has_attn);

    mma_gemm<1><<<gemm_grid, 256, GEMM_SMEM_BYTES>>>(pctx, Wfc, bfc, query, pyp);

    ln_kernel<<<MROWS, 256>>>(pyp, gamma, beta, out_y);
}